// round 15
// baseline (speedup 1.0000x reference)
#include <cuda_runtime.h>
#include <cuda_bf16.h>
#include <stddef.h>

#define S_LEN 16384
#define T_TAGS 1024
#define BEAM 64
#define NSTEP (S_LEN - 1)      // 16383
#define CH_L 128
#define NCH 128
#define LOG2E_F 1.4426950408889634f

// fast MUFU intrinsics (guaranteed single EX2/LG2)
__device__ __forceinline__ float ex2_approx(float x) {
    float y;
    asm("ex2.approx.f32 %0, %1;" : "=f"(y) : "f"(x));
    return y;
}
__device__ __forceinline__ float lg2_approx(float x) {
    float y;
    asm("lg2.approx.f32 %0, %1;" : "=f"(y) : "f"(x));
    return y;
}

// ---------------- scratch (device globals: no allocation allowed) ----------------
__device__ float         g_bsc[S_LEN * BEAM];          // top-64 scores per row (jax order)
__device__ int           g_btag[S_LEN * BEAM];         // top-64 tag indices per row
__device__ float         g_Wseq[NSTEP * BEAM * BEAM];  // Wseq[i][c][p] = weights[pt_i[p]][ct_i[c]] (exact, for Viterbi)
__device__ float         g_Wf2[NSTEP * BEAM * BEAM];   // (cs[c]+w[c][p]) * log2(e)  (for forward)
__device__ unsigned char g_bps[NSTEP * BEAM];          // backpointers
__device__ unsigned char g_allmap[NSTEP * BEAM];       // per-step composed backtrack maps
__device__ float         g_vit[BEAM];
__device__ float         g_fwd[BEAM];                  // final forward, log2-domain, relative (raw r)
__device__ double        g_K2;                         // accumulated log2 rebase
__device__ unsigned char g_Barr[NCH];                  // chunk-boundary best indices
__device__ float         g_logZ;
__device__ float         g_partials[64];

// monotonic float<->uint mapping for sorting
__device__ __forceinline__ unsigned fmap(float x) {
    unsigned u = __float_as_uint(x);
    return u ^ (((unsigned)((int)u >> 31)) | 0x80000000u);
}

// ---------------- Phase 1: exact top-64 per row, jax ordering (bitonic) ----------------
__global__ void __launch_bounds__(512) topk_kernel(const float* __restrict__ scores) {
    __shared__ unsigned long long keys[T_TAGS];
    int row = blockIdx.x;
    const float* rp = scores + (size_t)row * T_TAGS;
    int tid = threadIdx.x;
    for (int e = tid; e < T_TAGS; e += 512) {
        unsigned u = fmap(rp[e]);
        // key ascending == (value descending, index ascending) -> matches jax.lax.top_k
        keys[e] = ((unsigned long long)(~u) << 32) | (unsigned)e;
    }
    __syncthreads();
    for (int k = 2; k <= T_TAGS; k <<= 1) {
        for (int j = k >> 1; j > 0; j >>= 1) {
            #pragma unroll
            for (int r = 0; r < 2; ++r) {
                int i = tid + r * 512;
                int ixj = i ^ j;
                if (ixj > i) {
                    unsigned long long a = keys[i], b = keys[ixj];
                    bool up = ((i & k) == 0);
                    if ((a > b) == up) { keys[i] = b; keys[ixj] = a; }
                }
            }
            __syncthreads();
        }
    }
    if (tid < BEAM) {
        unsigned long long kk = keys[tid];
        int idx = (int)(kk & 0xffffffffu);
        g_btag[row * BEAM + tid] = idx;
        g_bsc[row * BEAM + tid]  = rp[idx];   // exact original value
    }
}

// ---------------- Phase 2: pre-gather transition matrices (full chip) ----------------
__global__ void __launch_bounds__(256) gather_kernel(const float* __restrict__ weights) {
    __shared__ int pt[BEAM], ct[BEAM];
    __shared__ float csn[BEAM];
    int i = blockIdx.x;                 // step 0..NSTEP-1
    int tid = threadIdx.x;
    if (tid < BEAM) {
        pt[tid] = g_btag[i * BEAM + tid];
    } else if (tid < 2 * BEAM) {
        int c = tid - BEAM;
        ct[c]  = g_btag[(i + 1) * BEAM + c];
        csn[c] = g_bsc[(i + 1) * BEAM + c];
    }
    __syncthreads();
    float* outv = g_Wseq + (size_t)i * (BEAM * BEAM);
    float* outf = g_Wf2  + (size_t)i * (BEAM * BEAM);
    #pragma unroll 4
    for (int e = tid; e < BEAM * BEAM; e += 256) {
        int c = e >> 6, p = e & 63;
        float w = weights[(size_t)pt[p] * T_TAGS + ct[c]];
        outv[e] = w;
        outf[e] = (csn[c] + w) * LOG2E_F;
    }
}

// ---------------- Phase 3: sequential scans, two CTAs (Viterbi SM + forward SM) ----------------
__global__ void __launch_bounds__(256, 1) scan_kernel() {
    __shared__ float sA[2][BEAM];
    const unsigned FULL = 0xffffffffu;
    int tid = threadIdx.x;
    int c = tid >> 2;          // column 0..63
    int q = tid & 3;           // quarter of rows
    int p0 = q * 16;

    if (blockIdx.x == 0) {
        // ================= Viterbi (exact) =================
        if (tid < BEAM) sA[0][tid] = g_bsc[tid];
        __syncthreads();

        float4 Wb[2][4];
        float  csb[2];
        #pragma unroll
        for (int s = 0; s < 2; ++s) {
            const float4* Wp = (const float4*)(g_Wseq + (size_t)s * 4096 + c * 64 + p0);
            Wb[s][0] = Wp[0]; Wb[s][1] = Wp[1]; Wb[s][2] = Wp[2]; Wb[s][3] = Wp[3];
            csb[s] = g_bsc[(s + 1) * BEAM + c];
        }

        for (int i = 0; i < NSTEP; ++i) {
            int cur = i & 1;
            float w[16];
            ((float4*)w)[0] = Wb[cur][0];
            ((float4*)w)[1] = Wb[cur][1];
            ((float4*)w)[2] = Wb[cur][2];
            ((float4*)w)[3] = Wb[cur][3];
            float cs = csb[cur];

            int pf = i + 2;
            if (pf < NSTEP) {
                const float4* Wp = (const float4*)(g_Wseq + (size_t)pf * 4096 + c * 64 + p0);
                Wb[cur][0] = Wp[0]; Wb[cur][1] = Wp[1]; Wb[cur][2] = Wp[2]; Wb[cur][3] = Wp[3];
                csb[cur] = g_bsc[(pf + 1) * BEAM + c];
            }

            const float* vin = sA[cur];
            float vv[16];
            {
                const float4* vf = (const float4*)(vin + p0);
                float4 a = vf[0], b = vf[1], d = vf[2], e = vf[3];
                float vr[16] = {a.x,a.y,a.z,a.w, b.x,b.y,b.z,b.w, d.x,d.y,d.z,d.w, e.x,e.y,e.z,e.w};
                #pragma unroll
                for (int k = 0; k < 16; ++k)
                    vv[k] = __fadd_rn(__fadd_rn(vr[k], cs), w[k]);   // exact: (vit+cs)+w
            }
            // in-thread leftmost-argmax tree over 16 (strict > keeps lower p on ties)
            float bv[8]; int bi[8];
            #pragma unroll
            for (int k = 0; k < 8; ++k) {
                bool r = vv[2*k+1] > vv[2*k];
                bv[k] = r ? vv[2*k+1] : vv[2*k];
                bi[k] = r ? (p0 + 2*k + 1) : (p0 + 2*k);
            }
            float cv[4]; int ci[4];
            #pragma unroll
            for (int k = 0; k < 4; ++k) {
                bool r = bv[2*k+1] > bv[2*k];
                cv[k] = r ? bv[2*k+1] : bv[2*k];
                ci[k] = r ? bi[2*k+1] : bi[2*k];
            }
            float dv[2]; int di[2];
            #pragma unroll
            for (int k = 0; k < 2; ++k) {
                bool r = cv[2*k+1] > cv[2*k];
                dv[k] = r ? cv[2*k+1] : cv[2*k];
                di[k] = r ? ci[2*k+1] : ci[2*k];
            }
            bool r0 = dv[1] > dv[0];
            float bestv = r0 ? dv[1] : dv[0];
            int   besti = r0 ? di[1] : di[0];

            // cross-lane combine within column (4 lanes), preserving first-index semantics
            {
                float ov = __shfl_xor_sync(FULL, bestv, 1);
                int   oi = __shfl_xor_sync(FULL, besti, 1);
                bool take = (q & 1) ? (ov >= bestv) : (ov > bestv);
                if (take) { bestv = ov; besti = oi; }
                ov = __shfl_xor_sync(FULL, bestv, 2);
                oi = __shfl_xor_sync(FULL, besti, 2);
                take = (q & 2) ? (ov >= bestv) : (ov > bestv);
                if (take) { bestv = ov; besti = oi; }
            }
            if (q == 0) {
                sA[cur ^ 1][c] = bestv;
                g_bps[(size_t)i * BEAM + c] = (unsigned char)besti;
            }
            __syncthreads();
        }
        if (tid < BEAM) g_vit[tid] = sA[NSTEP & 1][tid];
    } else {
        // ================= Forward (log2 domain, approximate OK) =================
        if (tid < BEAM) sA[0][tid] = g_bsc[tid] * LOG2E_F;
        __syncthreads();

        float4 Wb[2][4];
        #pragma unroll
        for (int s = 0; s < 2; ++s) {
            const float4* Wp = (const float4*)(g_Wf2 + (size_t)s * 4096 + c * 64 + p0);
            Wb[s][0] = Wp[0]; Wb[s][1] = Wp[1]; Wb[s][2] = Wp[2]; Wb[s][3] = Wp[3];
        }
        double K2 = 0.0;

        for (int i = 0; i < NSTEP; ++i) {
            int cur = i & 1;
            float w[16];
            ((float4*)w)[0] = Wb[cur][0];
            ((float4*)w)[1] = Wb[cur][1];
            ((float4*)w)[2] = Wb[cur][2];
            ((float4*)w)[3] = Wb[cur][3];

            int pf = i + 2;
            if (pf < NSTEP) {
                const float4* Wp = (const float4*)(g_Wf2 + (size_t)pf * 4096 + c * 64 + p0);
                Wb[cur][0] = Wp[0]; Wb[cur][1] = Wp[1]; Wb[cur][2] = Wp[2]; Wb[cur][3] = Wp[3];
            }

            const float* fin = sA[cur];
            float base = fin[0];               // per-step rebase (broadcast LDS)
            if (tid == 0) K2 += (double)base;

            float e[16];
            {
                const float4* ff = (const float4*)(fin + p0);
                float4 a = ff[0], b = ff[1], d = ff[2], g = ff[3];
                float fr[16] = {a.x,a.y,a.z,a.w, b.x,b.y,b.z,b.w, d.x,d.y,d.z,d.w, g.x,g.y,g.z,g.w};
                #pragma unroll
                for (int k = 0; k < 16; ++k)
                    e[k] = ex2_approx((fr[k] - base) + w[k]);
            }
            // tree sum (reassociation fine)
            #pragma unroll
            for (int k = 0; k < 8; ++k) e[k] = e[2*k] + e[2*k+1];
            #pragma unroll
            for (int k = 0; k < 4; ++k) e[k] = e[2*k] + e[2*k+1];
            float s = (e[0] + e[1]) + (e[2] + e[3]);
            s += __shfl_xor_sync(FULL, s, 1);
            s += __shfl_xor_sync(FULL, s, 2);
            if (q == 0) sA[cur ^ 1][c] = lg2_approx(s);
            __syncthreads();
        }
        if (tid < BEAM) g_fwd[tid] = sA[NSTEP & 1][tid];
        if (tid == 0)   g_K2 = K2;
    }
}

// ---------------- Phase 4: parallel backtrack (chunked map composition) ----------------
__global__ void __launch_bounds__(64) chunkmap_kernel() {
    __shared__ unsigned char sbp[CH_L * BEAM];
    int j = blockIdx.x;
    int lo = j * CH_L;
    int hi = min(lo + CH_L, NSTEP);
    int n = hi - lo;
    int tid = threadIdx.x;   // = column c at time hi
    for (int e = tid; e < n * BEAM; e += 64) sbp[e] = g_bps[(size_t)lo * BEAM + e];
    __syncthreads();
    int m = tid;
    for (int ii = n - 1; ii >= 0; --ii) {
        m = sbp[ii * BEAM + m];
        g_allmap[(size_t)(lo + ii) * BEAM + tid] = (unsigned char)m;
    }
}

__global__ void finish_kernel() {
    if (threadIdx.x != 0 || blockIdx.x != 0) return;
    // last = first-index argmax of final vit
    float best = g_vit[0]; int last = 0;
    for (int cc = 1; cc < BEAM; ++cc) { float v = g_vit[cc]; if (v > best) { best = v; last = cc; } }
    int b = last;
    g_Barr[NCH - 1] = (unsigned char)b;
    for (int j = NCH - 1; j >= 1; --j) {
        b = g_allmap[(size_t)(j * CH_L) * BEAM + b];
        g_Barr[j - 1] = (unsigned char)b;
    }
    // logZ = ln2 * (K2 + log2(sum_c 2^r[c]))
    double s = 0.0;
    for (int cc = 0; cc < BEAM; ++cc) s += exp2((double)g_fwd[cc]);
    g_logZ = (float)(0.693147180559945309 * (g_K2 + log2(s)));
}

__global__ void __launch_bounds__(256) emit_kernel(float* __restrict__ out) {
    int s = blockIdx.x * 256 + threadIdx.x;
    if (s >= S_LEN) return;
    int bi;
    if (s == S_LEN - 1) bi = g_Barr[NCH - 1];
    else                bi = g_allmap[(size_t)s * BEAM + g_Barr[s >> 7]];
    out[s] = (float)g_btag[s * BEAM + bi];
}

// ---------------- Phase 5: deterministic base+crf partial sums ----------------
__global__ void __launch_bounds__(256) partial_kernel(const float* __restrict__ scores,
                                                      const float* __restrict__ weights,
                                                      const int* __restrict__ tags) {
    __shared__ float red[256];
    int s = blockIdx.x * 256 + threadIdx.x;    // 64 blocks * 256 = 16384 exactly
    int t0 = tags[s];
    float acc = scores[(size_t)s * T_TAGS + t0];
    if (s < S_LEN - 1) acc += weights[(size_t)t0 * T_TAGS + tags[s + 1]];
    red[threadIdx.x] = acc;
    __syncthreads();
    for (int o = 128; o; o >>= 1) {
        if (threadIdx.x < o) red[threadIdx.x] += red[threadIdx.x + o];
        __syncthreads();
    }
    if (threadIdx.x == 0) g_partials[blockIdx.x] = red[0];
}

__global__ void final2_kernel(float* __restrict__ out) {
    if (threadIdx.x != 0 || blockIdx.x != 0) return;
    float t = 0.f;
    for (int b = 0; b < 64; ++b) t += g_partials[b];
    out[S_LEN] = g_logZ - t;    // -logprob = logZ - base - crf
}

// ---------------- launcher ----------------
extern "C" void kernel_launch(void* const* d_in, const int* in_sizes, int n_in,
                              void* d_out, int out_size) {
    const float* scores  = (const float*)d_in[0];
    const float* weights = (const float*)d_in[1];
    const int*   tags    = (const int*)d_in[2];
    float* out = (float*)d_out;

    topk_kernel<<<S_LEN, 512>>>(scores);
    gather_kernel<<<NSTEP, 256>>>(weights);
    scan_kernel<<<2, 256>>>();
    chunkmap_kernel<<<NCH, 64>>>();
    finish_kernel<<<1, 32>>>();
    emit_kernel<<<(S_LEN + 255) / 256, 256>>>(out);
    partial_kernel<<<64, 256>>>(scores, weights, tags);
    final2_kernel<<<1, 32>>>(out);
}

// round 16
// speedup vs baseline: 1.2289x; 1.2289x over previous
#include <cuda_runtime.h>
#include <cuda_bf16.h>
#include <stddef.h>

#define S_LEN 16384
#define T_TAGS 1024
#define BEAM 64
#define NSTEP (S_LEN - 1)      // 16383 = 4*4095 + 3
#define CH_L 128
#define NCH 128
#define LOG2E_F 1.4426950408889634f

__device__ __forceinline__ float ex2_approx(float x) {
    float y; asm("ex2.approx.f32 %0, %1;" : "=f"(y) : "f"(x)); return y;
}
__device__ __forceinline__ float lg2_approx(float x) {
    float y; asm("lg2.approx.f32 %0, %1;" : "=f"(y) : "f"(x)); return y;
}
#define BARH(id) asm volatile("bar.sync %0, 256;" :: "r"(id) : "memory")

// ---------------- scratch ----------------
__device__ float         g_bsc[S_LEN * BEAM];
__device__ int           g_btag[S_LEN * BEAM];
__device__ float         g_Wseq[NSTEP * BEAM * BEAM];  // Wseq[i][c][p] = weights[pt_i[p]][ct_i[c]]
__device__ unsigned char g_bps[NSTEP * BEAM];
__device__ unsigned char g_allmap[NSTEP * BEAM];
__device__ float         g_vit[BEAM];
__device__ float         g_fwd[BEAM];
__device__ double        g_K2;
__device__ unsigned char g_Barr[NCH];
__device__ float         g_logZ;
__device__ float         g_partials[64];

__device__ __forceinline__ unsigned fmap(float x) {
    unsigned u = __float_as_uint(x);
    return u ^ (((unsigned)((int)u >> 31)) | 0x80000000u);
}

// ---------------- Phase 1: exact top-64 per row, jax ordering ----------------
__global__ void __launch_bounds__(512) topk_kernel(const float* __restrict__ scores) {
    __shared__ unsigned long long keys[T_TAGS];
    int row = blockIdx.x;
    const float* rp = scores + (size_t)row * T_TAGS;
    int tid = threadIdx.x;
    for (int e = tid; e < T_TAGS; e += 512) {
        unsigned u = fmap(rp[e]);
        keys[e] = ((unsigned long long)(~u) << 32) | (unsigned)e;
    }
    __syncthreads();
    for (int k = 2; k <= T_TAGS; k <<= 1) {
        for (int j = k >> 1; j > 0; j >>= 1) {
            #pragma unroll
            for (int r = 0; r < 2; ++r) {
                int i = tid + r * 512;
                int ixj = i ^ j;
                if (ixj > i) {
                    unsigned long long a = keys[i], b = keys[ixj];
                    bool up = ((i & k) == 0);
                    if ((a > b) == up) { keys[i] = b; keys[ixj] = a; }
                }
            }
            __syncthreads();
        }
    }
    if (tid < BEAM) {
        unsigned long long kk = keys[tid];
        int idx = (int)(kk & 0xffffffffu);
        g_btag[row * BEAM + tid] = idx;
        g_bsc[row * BEAM + tid]  = rp[idx];
    }
}

// ---------------- Phase 2: pre-gather (single array) ----------------
__global__ void __launch_bounds__(256) gather_kernel(const float* __restrict__ weights) {
    __shared__ int pt[BEAM], ct[BEAM];
    int i = blockIdx.x;
    int tid = threadIdx.x;
    if (tid < BEAM)           pt[tid]      = g_btag[i * BEAM + tid];
    else if (tid < 2 * BEAM)  ct[tid - 64] = g_btag[(i + 1) * BEAM + (tid - 64)];
    __syncthreads();
    float* outv = g_Wseq + (size_t)i * (BEAM * BEAM);
    #pragma unroll
    for (int k = 0; k < 16; ++k) {
        int e = tid + k * 256;
        int c = e >> 6, p = e & 63;
        outv[e] = weights[(size_t)pt[p] * T_TAGS + ct[c]];
    }
}

// ---------------- Phase 3: merged sequential scan (one 512-thread CTA) ----------------
__global__ void __launch_bounds__(512, 1) scan_kernel() {
    __shared__ float svit[2][BEAM];
    __shared__ float sfwd[2][BEAM];
    const unsigned FULL = 0xffffffffu;
    int tid = threadIdx.x;
    bool isf = (tid >= 256);
    int t = tid & 255;
    int c = t >> 2;
    int q = t & 3;
    int p0 = q * 16;

    if (!isf) {
        // ================= Viterbi half (exact) =================
        if (t < BEAM) svit[0][t] = g_bsc[t];
        BARH(1);

        float4 Wb[4][4];
        float  csb[4];
        #pragma unroll
        for (int s = 0; s < 4; ++s) {
            const float4* Wp = (const float4*)(g_Wseq + (size_t)s * 4096 + c * 64 + p0);
            Wb[s][0] = Wp[0]; Wb[s][1] = Wp[1]; Wb[s][2] = Wp[2]; Wb[s][3] = Wp[3];
            csb[s] = g_bsc[(s + 1) * BEAM + c];
        }

        int i = 0;
        #pragma unroll 1
        for (int it = 0; it < 4096; ++it) {
            #pragma unroll
            for (int j = 0; j < 4; ++j) {
                if (it == 4095 && j == 3) break;   // 16383 steps total
                float w[16];
                ((float4*)w)[0] = Wb[j][0]; ((float4*)w)[1] = Wb[j][1];
                ((float4*)w)[2] = Wb[j][2]; ((float4*)w)[3] = Wb[j][3];
                float cs = csb[j];

                int pf = i + 4;
                if (pf < NSTEP) {
                    const float4* Wp = (const float4*)(g_Wseq + (size_t)pf * 4096 + c * 64 + p0);
                    Wb[j][0] = Wp[0]; Wb[j][1] = Wp[1]; Wb[j][2] = Wp[2]; Wb[j][3] = Wp[3];
                    csb[j] = g_bsc[(pf + 1) * BEAM + c];
                }

                const float* vin = svit[j & 1];
                float vv[16];
                {
                    const float4* vf = (const float4*)(vin + p0);
                    float4 a = vf[0], b = vf[1], d = vf[2], e = vf[3];
                    float vr[16] = {a.x,a.y,a.z,a.w, b.x,b.y,b.z,b.w,
                                    d.x,d.y,d.z,d.w, e.x,e.y,e.z,e.w};
                    #pragma unroll
                    for (int k = 0; k < 16; ++k)
                        vv[k] = __fadd_rn(__fadd_rn(vr[k], cs), w[k]);
                }
                // leftmost-argmax tree (strict > keeps lower p on ties)
                float bv[8]; int bi[8];
                #pragma unroll
                for (int k = 0; k < 8; ++k) {
                    bool r = vv[2*k+1] > vv[2*k];
                    bv[k] = r ? vv[2*k+1] : vv[2*k];
                    bi[k] = r ? (p0 + 2*k + 1) : (p0 + 2*k);
                }
                float cv[4]; int ci[4];
                #pragma unroll
                for (int k = 0; k < 4; ++k) {
                    bool r = bv[2*k+1] > bv[2*k];
                    cv[k] = r ? bv[2*k+1] : bv[2*k];
                    ci[k] = r ? bi[2*k+1] : bi[2*k];
                }
                float dv0, dv1; int di0, di1;
                { bool r = cv[1] > cv[0]; dv0 = r ? cv[1] : cv[0]; di0 = r ? ci[1] : ci[0]; }
                { bool r = cv[3] > cv[2]; dv1 = r ? cv[3] : cv[2]; di1 = r ? ci[3] : ci[2]; }
                bool r0 = dv1 > dv0;
                float bestv = r0 ? dv1 : dv0;
                int   besti = r0 ? di1 : di0;

                {
                    float ov = __shfl_xor_sync(FULL, bestv, 1);
                    int   oi = __shfl_xor_sync(FULL, besti, 1);
                    bool take = (q & 1) ? (ov >= bestv) : (ov > bestv);
                    if (take) { bestv = ov; besti = oi; }
                    ov = __shfl_xor_sync(FULL, bestv, 2);
                    oi = __shfl_xor_sync(FULL, besti, 2);
                    take = (q & 2) ? (ov >= bestv) : (ov > bestv);
                    if (take) { bestv = ov; besti = oi; }
                }
                if (q == 0) {
                    svit[(j & 1) ^ 1][c] = bestv;
                    g_bps[(size_t)i * BEAM + c] = (unsigned char)besti;
                }
                BARH(1);
                ++i;
            }
        }
        if (t < BEAM) g_vit[t] = svit[NSTEP & 1][t];
    } else {
        // ================= Forward half (log2 domain) =================
        if (t < BEAM) sfwd[0][t] = g_bsc[t] * LOG2E_F;
        BARH(2);

        float4 Wb[4][4];
        float  csb[4];
        #pragma unroll
        for (int s = 0; s < 4; ++s) {
            const float4* Wp = (const float4*)(g_Wseq + (size_t)s * 4096 + c * 64 + p0);
            Wb[s][0] = Wp[0]; Wb[s][1] = Wp[1]; Wb[s][2] = Wp[2]; Wb[s][3] = Wp[3];
            csb[s] = g_bsc[(s + 1) * BEAM + c];
        }
        double K2 = 0.0;

        int i = 0;
        #pragma unroll 1
        for (int it = 0; it < 4096; ++it) {
            #pragma unroll
            for (int j = 0; j < 4; ++j) {
                if (it == 4095 && j == 3) break;
                float w[16];
                ((float4*)w)[0] = Wb[j][0]; ((float4*)w)[1] = Wb[j][1];
                ((float4*)w)[2] = Wb[j][2]; ((float4*)w)[3] = Wb[j][3];
                float cs = csb[j];

                int pf = i + 4;
                if (pf < NSTEP) {
                    const float4* Wp = (const float4*)(g_Wseq + (size_t)pf * 4096 + c * 64 + p0);
                    Wb[j][0] = Wp[0]; Wb[j][1] = Wp[1]; Wb[j][2] = Wp[2]; Wb[j][3] = Wp[3];
                    csb[j] = g_bsc[(pf + 1) * BEAM + c];
                }

                const float* fin = sfwd[j & 1];
                float base = fin[0];
                if (t == 0) K2 += (double)base;
                float u = __fmaf_rn(cs, LOG2E_F, -base);   // cs*L - base

                float e[16];
                {
                    const float4* ff = (const float4*)(fin + p0);
                    float4 a = ff[0], b = ff[1], d = ff[2], g = ff[3];
                    float fr[16] = {a.x,a.y,a.z,a.w, b.x,b.y,b.z,b.w,
                                    d.x,d.y,d.z,d.w, g.x,g.y,g.z,g.w};
                    #pragma unroll
                    for (int k = 0; k < 16; ++k)
                        e[k] = ex2_approx(__fmaf_rn(w[k], LOG2E_F, fr[k] + u));
                }
                #pragma unroll
                for (int k = 0; k < 8; ++k) e[k] = e[2*k] + e[2*k+1];
                #pragma unroll
                for (int k = 0; k < 4; ++k) e[k] = e[2*k] + e[2*k+1];
                float s = (e[0] + e[1]) + (e[2] + e[3]);
                s += __shfl_xor_sync(FULL, s, 1);
                s += __shfl_xor_sync(FULL, s, 2);
                if (q == 0) sfwd[(j & 1) ^ 1][c] = lg2_approx(s);
                BARH(2);
                ++i;
            }
        }
        if (t < BEAM) g_fwd[t] = sfwd[NSTEP & 1][t];
        if (t == 0)   g_K2 = K2;
    }
}

// ---------------- Phase 4: parallel backtrack ----------------
__global__ void __launch_bounds__(64) chunkmap_kernel() {
    __shared__ unsigned char sbp[CH_L * BEAM];
    int j = blockIdx.x;
    int lo = j * CH_L;
    int hi = min(lo + CH_L, NSTEP);
    int n = hi - lo;
    int tid = threadIdx.x;
    for (int e = tid; e < n * BEAM; e += 64) sbp[e] = g_bps[(size_t)lo * BEAM + e];
    __syncthreads();
    int m = tid;
    for (int ii = n - 1; ii >= 0; --ii) {
        m = sbp[ii * BEAM + m];
        g_allmap[(size_t)(lo + ii) * BEAM + tid] = (unsigned char)m;
    }
}

__global__ void finish_kernel() {
    if (threadIdx.x != 0 || blockIdx.x != 0) return;
    float best = g_vit[0]; int last = 0;
    for (int cc = 1; cc < BEAM; ++cc) { float v = g_vit[cc]; if (v > best) { best = v; last = cc; } }
    int b = last;
    g_Barr[NCH - 1] = (unsigned char)b;
    for (int j = NCH - 1; j >= 1; --j) {
        b = g_allmap[(size_t)(j * CH_L) * BEAM + b];
        g_Barr[j - 1] = (unsigned char)b;
    }
    double s = 0.0;
    for (int cc = 0; cc < BEAM; ++cc) s += exp2((double)g_fwd[cc]);
    g_logZ = (float)(0.693147180559945309 * (g_K2 + log2(s)));
}

__global__ void __launch_bounds__(256) emit_kernel(float* __restrict__ out) {
    int s = blockIdx.x * 256 + threadIdx.x;
    if (s >= S_LEN) return;
    int bi;
    if (s == S_LEN - 1) bi = g_Barr[NCH - 1];
    else                bi = g_allmap[(size_t)s * BEAM + g_Barr[s >> 7]];
    out[s] = (float)g_btag[s * BEAM + bi];
}

// ---------------- Phase 5: deterministic base+crf partial sums ----------------
__global__ void __launch_bounds__(256) partial_kernel(const float* __restrict__ scores,
                                                      const float* __restrict__ weights,
                                                      const int* __restrict__ tags) {
    __shared__ float red[256];
    int s = blockIdx.x * 256 + threadIdx.x;
    int t0 = tags[s];
    float acc = scores[(size_t)s * T_TAGS + t0];
    if (s < S_LEN - 1) acc += weights[(size_t)t0 * T_TAGS + tags[s + 1]];
    red[threadIdx.x] = acc;
    __syncthreads();
    for (int o = 128; o; o >>= 1) {
        if (threadIdx.x < o) red[threadIdx.x] += red[threadIdx.x + o];
        __syncthreads();
    }
    if (threadIdx.x == 0) g_partials[blockIdx.x] = red[0];
}

__global__ void final2_kernel(float* __restrict__ out) {
    if (threadIdx.x != 0 || blockIdx.x != 0) return;
    float t = 0.f;
    for (int b = 0; b < 64; ++b) t += g_partials[b];
    out[S_LEN] = g_logZ - t;
}

// ---------------- launcher (scan placed at launch index 3 for ncu capture) ----------------
extern "C" void kernel_launch(void* const* d_in, const int* in_sizes, int n_in,
                              void* d_out, int out_size) {
    const float* scores  = (const float*)d_in[0];
    const float* weights = (const float*)d_in[1];
    const int*   tags    = (const int*)d_in[2];
    float* out = (float*)d_out;

    topk_kernel<<<S_LEN, 512>>>(scores);                 // 0
    gather_kernel<<<NSTEP, 256>>>(weights);              // 1
    partial_kernel<<<64, 256>>>(scores, weights, tags);  // 2 (independent)
    scan_kernel<<<1, 512>>>();                           // 3  <- hoped ncu capture slot
    chunkmap_kernel<<<NCH, 64>>>();                      // 4
    finish_kernel<<<1, 32>>>();                          // 5
    emit_kernel<<<(S_LEN + 255) / 256, 256>>>(out);      // 6
    final2_kernel<<<1, 32>>>(out);                       // 7
}

// round 17
// speedup vs baseline: 2.1188x; 1.7242x over previous
#include <cuda_runtime.h>
#include <cuda_bf16.h>
#include <stddef.h>

#define S_LEN 16384
#define T_TAGS 1024
#define BEAM 64
#define NSTEP (S_LEN - 1)      // 16383 = 8*2047 + 7
#define CH_L 128
#define NCH 128
#define LOG2E_F 1.4426950408889634f

__device__ __forceinline__ float ex2_approx(float x) {
    float y; asm("ex2.approx.f32 %0, %1;" : "=f"(y) : "f"(x)); return y;
}
__device__ __forceinline__ float lg2_approx(float x) {
    float y; asm("lg2.approx.f32 %0, %1;" : "=f"(y) : "f"(x)); return y;
}

// ---------------- scratch ----------------
__device__ float         g_bsc[S_LEN * BEAM];
__device__ int           g_btag[S_LEN * BEAM];
__device__ float         g_Wseq[NSTEP * BEAM * BEAM];  // Wseq[i][c][p]
__device__ unsigned char g_bps[NSTEP * BEAM];
__device__ unsigned char g_allmap[NSTEP * BEAM];
__device__ float         g_vit[BEAM];
__device__ float         g_fwd[BEAM];
__device__ double        g_K2;
__device__ unsigned char g_Barr[NCH];
__device__ float         g_logZ;
__device__ float         g_partials[128];

// monotonic float<->uint mapping (exact, invertible)
__device__ __forceinline__ unsigned fmap(float x) {
    unsigned u = __float_as_uint(x);
    return u ^ (((unsigned)((int)u >> 31)) | 0x80000000u);
}
__device__ __forceinline__ float funmap(unsigned m) {
    unsigned s = (m & 0x80000000u) ? 0x80000000u : 0xFFFFFFFFu;
    return __uint_as_float(m ^ s);
}

// ---------------- Phase 1: exact top-64 via histogram select + small sort ----------------
__global__ void __launch_bounds__(256) topk_kernel(const float* __restrict__ scores) {
    __shared__ int hist[4096];
    __shared__ int cs[256];
    __shared__ unsigned long long cand[1024];
    __shared__ int sB, sN;

    int row = blockIdx.x;
    int tid = threadIdx.x;
    const float* rp = scores + (size_t)row * T_TAGS;

    // coalesced load: 4 contiguous values per thread
    float4 v4 = ((const float4*)rp)[tid];
    float val[4] = {v4.x, v4.y, v4.z, v4.w};
    unsigned key[4];
    #pragma unroll
    for (int k = 0; k < 4; ++k) key[k] = fmap(val[k]);

    #pragma unroll
    for (int k = 0; k < 16; ++k) hist[tid + k * 256] = 0;
    if (tid == 0) sN = 0;
    __syncthreads();

    #pragma unroll
    for (int k = 0; k < 4; ++k) atomicAdd(&hist[key[k] >> 20], 1);
    __syncthreads();

    // chunk sums: thread t covers bins [t*16, t*16+16)
    {
        int s = 0;
        #pragma unroll
        for (int k = 0; k < 16; ++k) s += hist[tid * 16 + k];
        cs[tid] = s;
    }
    __syncthreads();

    if (tid < 32) {
        const unsigned FULL = 0xffffffffu;
        int l = tid;
        int gs = 0;
        #pragma unroll
        for (int r = 0; r < 8; ++r) gs += cs[l * 8 + r];
        // suffix-inclusive (from high lanes) scan: suf[l] = sum_{g>=l} gs[g]
        int suf = gs;
        #pragma unroll
        for (int o = 1; o < 32; o <<= 1) {
            int v = __shfl_down_sync(FULL, suf, o);
            if (l + o < 32) suf += v;
        }
        unsigned mask = __ballot_sync(FULL, suf >= BEAM);
        int lstar = 31 - __clz(mask);   // largest group with suffix >= 64
        if (l == lstar) {
            int acc = suf - gs;         // count strictly above this group
            int B = 0;
            for (int ch = l * 8 + 7; ch >= l * 8; --ch) {
                int nc = acc + cs[ch];
                if (nc >= BEAM) {
                    for (int b = ch * 16 + 15; b >= ch * 16; --b) {
                        acc += hist[b];
                        if (acc >= BEAM) { B = b; break; }
                    }
                    break;
                }
                acc = nc;
            }
            sB = B;
        }
    }
    __syncthreads();
    int B = sB;

    // compact candidates (bin >= B). key ascending-sort order: (~fmap, index)
    #pragma unroll
    for (int k = 0; k < 4; ++k) {
        if ((int)(key[k] >> 20) >= B) {
            int idx = atomicAdd(&sN, 1);
            cand[idx] = ((unsigned long long)(~key[k]) << 32) | (unsigned)(tid * 4 + k);
        }
    }
    __syncthreads();
    int n = sN;
    int np2 = 1 << (32 - __clz(n - 1));    // n >= 64 always
    for (int e = n + tid; e < np2; e += 256) cand[e] = 0xffffffffffffffffULL;
    __syncthreads();

    // bitonic sort np2 (typically 128) ascending
    for (int k = 2; k <= np2; k <<= 1) {
        for (int j = k >> 1; j > 0; j >>= 1) {
            for (int i = tid; i < np2; i += 256) {
                int ixj = i ^ j;
                if (ixj > i) {
                    unsigned long long a = cand[i], b = cand[ixj];
                    bool up = ((i & k) == 0);
                    if ((a > b) == up) { cand[i] = b; cand[ixj] = a; }
                }
            }
            __syncthreads();
        }
    }

    if (tid < BEAM) {
        unsigned long long kk = cand[tid];
        unsigned mk = ~(unsigned)(kk >> 32);
        g_btag[row * BEAM + tid] = (int)(kk & 0xffffffffu);
        g_bsc[row * BEAM + tid]  = funmap(mk);
    }
}

// ---------------- Phase 2: pre-gather ----------------
__global__ void __launch_bounds__(256) gather_kernel(const float* __restrict__ weights) {
    __shared__ int pt[BEAM], ct[BEAM];
    int i = blockIdx.x;
    int tid = threadIdx.x;
    if (tid < BEAM)           pt[tid]      = g_btag[i * BEAM + tid];
    else if (tid < 2 * BEAM)  ct[tid - 64] = g_btag[(i + 1) * BEAM + (tid - 64)];
    __syncthreads();
    float* outv = g_Wseq + (size_t)i * (BEAM * BEAM);
    #pragma unroll
    for (int k = 0; k < 16; ++k) {
        int e = tid + k * 256;
        int c = e >> 6, p = e & 63;
        outv[e] = weights[(size_t)pt[p] * T_TAGS + ct[c]];
    }
}

// ---------------- Phase 3: sequential scans, 2 CTAs, depth-8 prefetch ----------------
__global__ void __launch_bounds__(256, 1) scan_kernel() {
    __shared__ float sA[2][BEAM];
    const unsigned FULL = 0xffffffffu;
    int t = threadIdx.x;
    int c = t >> 2;
    int q = t & 3;
    int p0 = q * 16;

    if (blockIdx.x == 0) {
        // ================= Viterbi (exact) =================
        if (t < BEAM) sA[0][t] = g_bsc[t];
        __syncthreads();

        float4 Wb[8][4];
        float  csb[8];
        #pragma unroll
        for (int s = 0; s < 8; ++s) {
            const float4* Wp = (const float4*)(g_Wseq + (size_t)s * 4096 + c * 64 + p0);
            Wb[s][0] = Wp[0]; Wb[s][1] = Wp[1]; Wb[s][2] = Wp[2]; Wb[s][3] = Wp[3];
            csb[s] = g_bsc[(s + 1) * BEAM + c];
        }

        int i = 0;
        #pragma unroll 1
        for (int it = 0; it < 2048; ++it) {
            #pragma unroll
            for (int j = 0; j < 8; ++j) {
                if (it == 2047 && j == 7) break;   // 16383 steps
                float w[16];
                ((float4*)w)[0] = Wb[j][0]; ((float4*)w)[1] = Wb[j][1];
                ((float4*)w)[2] = Wb[j][2]; ((float4*)w)[3] = Wb[j][3];
                float cs = csb[j];

                int pf = i + 8;
                if (pf < NSTEP) {
                    const float4* Wp = (const float4*)(g_Wseq + (size_t)pf * 4096 + c * 64 + p0);
                    Wb[j][0] = Wp[0]; Wb[j][1] = Wp[1]; Wb[j][2] = Wp[2]; Wb[j][3] = Wp[3];
                    csb[j] = g_bsc[(pf + 1) * BEAM + c];
                }

                const float* vin = sA[j & 1];
                float vv[16];
                {
                    const float4* vf = (const float4*)(vin + p0);
                    float4 a = vf[0], b = vf[1], d = vf[2], e = vf[3];
                    float vr[16] = {a.x,a.y,a.z,a.w, b.x,b.y,b.z,b.w,
                                    d.x,d.y,d.z,d.w, e.x,e.y,e.z,e.w};
                    #pragma unroll
                    for (int k = 0; k < 16; ++k)
                        vv[k] = __fadd_rn(__fadd_rn(vr[k], cs), w[k]);
                }
                // leftmost-argmax tree (strict > keeps lower p on ties)
                float bv[8]; int bi[8];
                #pragma unroll
                for (int k = 0; k < 8; ++k) {
                    bool r = vv[2*k+1] > vv[2*k];
                    bv[k] = r ? vv[2*k+1] : vv[2*k];
                    bi[k] = r ? (p0 + 2*k + 1) : (p0 + 2*k);
                }
                float cv[4]; int ci[4];
                #pragma unroll
                for (int k = 0; k < 4; ++k) {
                    bool r = bv[2*k+1] > bv[2*k];
                    cv[k] = r ? bv[2*k+1] : bv[2*k];
                    ci[k] = r ? bi[2*k+1] : bi[2*k];
                }
                float dv0, dv1; int di0, di1;
                { bool r = cv[1] > cv[0]; dv0 = r ? cv[1] : cv[0]; di0 = r ? ci[1] : ci[0]; }
                { bool r = cv[3] > cv[2]; dv1 = r ? cv[3] : cv[2]; di1 = r ? ci[3] : ci[2]; }
                bool r0 = dv1 > dv0;
                float bestv = r0 ? dv1 : dv0;
                int   besti = r0 ? di1 : di0;
                {
                    float ov = __shfl_xor_sync(FULL, bestv, 1);
                    int   oi = __shfl_xor_sync(FULL, besti, 1);
                    bool take = (q & 1) ? (ov >= bestv) : (ov > bestv);
                    if (take) { bestv = ov; besti = oi; }
                    ov = __shfl_xor_sync(FULL, bestv, 2);
                    oi = __shfl_xor_sync(FULL, besti, 2);
                    take = (q & 2) ? (ov >= bestv) : (ov > bestv);
                    if (take) { bestv = ov; besti = oi; }
                }
                if (q == 0) {
                    sA[(j & 1) ^ 1][c] = bestv;
                    g_bps[(size_t)i * BEAM + c] = (unsigned char)besti;
                }
                __syncthreads();
                ++i;
            }
        }
        if (t < BEAM) g_vit[t] = sA[NSTEP & 1][t];
    } else {
        // ================= Forward (log2 domain) =================
        if (t < BEAM) sA[0][t] = g_bsc[t] * LOG2E_F;
        __syncthreads();

        float4 Wb[8][4];
        float  csb[8];
        #pragma unroll
        for (int s = 0; s < 8; ++s) {
            const float4* Wp = (const float4*)(g_Wseq + (size_t)s * 4096 + c * 64 + p0);
            Wb[s][0] = Wp[0]; Wb[s][1] = Wp[1]; Wb[s][2] = Wp[2]; Wb[s][3] = Wp[3];
            csb[s] = g_bsc[(s + 1) * BEAM + c];
        }
        double K2 = 0.0;

        int i = 0;
        #pragma unroll 1
        for (int it = 0; it < 2048; ++it) {
            #pragma unroll
            for (int j = 0; j < 8; ++j) {
                if (it == 2047 && j == 7) break;
                float w[16];
                ((float4*)w)[0] = Wb[j][0]; ((float4*)w)[1] = Wb[j][1];
                ((float4*)w)[2] = Wb[j][2]; ((float4*)w)[3] = Wb[j][3];
                float cs = csb[j];

                int pf = i + 8;
                if (pf < NSTEP) {
                    const float4* Wp = (const float4*)(g_Wseq + (size_t)pf * 4096 + c * 64 + p0);
                    Wb[j][0] = Wp[0]; Wb[j][1] = Wp[1]; Wb[j][2] = Wp[2]; Wb[j][3] = Wp[3];
                    csb[j] = g_bsc[(pf + 1) * BEAM + c];
                }

                const float* fin = sA[j & 1];
                float base = fin[0];
                if (t == 0) K2 += (double)base;
                float u = __fmaf_rn(cs, LOG2E_F, -base);

                float e[16];
                {
                    const float4* ff = (const float4*)(fin + p0);
                    float4 a = ff[0], b = ff[1], d = ff[2], g = ff[3];
                    float fr[16] = {a.x,a.y,a.z,a.w, b.x,b.y,b.z,b.w,
                                    d.x,d.y,d.z,d.w, g.x,g.y,g.z,g.w};
                    #pragma unroll
                    for (int k = 0; k < 16; ++k)
                        e[k] = ex2_approx(__fmaf_rn(w[k], LOG2E_F, fr[k] + u));
                }
                #pragma unroll
                for (int k = 0; k < 8; ++k) e[k] = e[2*k] + e[2*k+1];
                #pragma unroll
                for (int k = 0; k < 4; ++k) e[k] = e[2*k] + e[2*k+1];
                float s = (e[0] + e[1]) + (e[2] + e[3]);
                s += __shfl_xor_sync(FULL, s, 1);
                s += __shfl_xor_sync(FULL, s, 2);
                if (q == 0) sA[(j & 1) ^ 1][c] = lg2_approx(s);
                __syncthreads();
                ++i;
            }
        }
        if (t < BEAM) g_fwd[t] = sA[NSTEP & 1][t];
        if (t == 0)   g_K2 = K2;
    }
}

// ---------------- Phase 4: parallel backtrack ----------------
__global__ void __launch_bounds__(64) chunkmap_kernel() {
    __shared__ unsigned char sbp[CH_L * BEAM];
    int j = blockIdx.x;
    int lo = j * CH_L;
    int hi = min(lo + CH_L, NSTEP);
    int n = hi - lo;
    int tid = threadIdx.x;
    for (int e = tid; e < n * BEAM; e += 64) sbp[e] = g_bps[(size_t)lo * BEAM + e];
    __syncthreads();
    int m = tid;
    for (int ii = n - 1; ii >= 0; --ii) {
        m = sbp[ii * BEAM + m];
        g_allmap[(size_t)(lo + ii) * BEAM + tid] = (unsigned char)m;
    }
}

__global__ void finish_kernel() {
    if (threadIdx.x != 0 || blockIdx.x != 0) return;
    float best = g_vit[0]; int last = 0;
    for (int cc = 1; cc < BEAM; ++cc) { float v = g_vit[cc]; if (v > best) { best = v; last = cc; } }
    int b = last;
    g_Barr[NCH - 1] = (unsigned char)b;
    for (int j = NCH - 1; j >= 1; --j) {
        b = g_allmap[(size_t)(j * CH_L) * BEAM + b];
        g_Barr[j - 1] = (unsigned char)b;
    }
    double s = 0.0;
    for (int cc = 0; cc < BEAM; ++cc) s += exp2((double)g_fwd[cc]);
    g_logZ = (float)(0.693147180559945309 * (g_K2 + log2(s)));
}

__global__ void __launch_bounds__(256) emit_kernel(float* __restrict__ out) {
    int s = blockIdx.x * 256 + threadIdx.x;
    if (s >= S_LEN) return;
    int bi;
    if (s == S_LEN - 1) bi = g_Barr[NCH - 1];
    else                bi = g_allmap[(size_t)s * BEAM + g_Barr[s >> 7]];
    out[s] = (float)g_btag[s * BEAM + bi];
}

// ---------------- Phase 5: deterministic base / crf partial sums (split) ----------------
__global__ void __launch_bounds__(256) partialA_kernel(const float* __restrict__ scores,
                                                       const int* __restrict__ tags) {
    __shared__ float red[256];
    int s = blockIdx.x * 256 + threadIdx.x;
    red[threadIdx.x] = scores[(size_t)s * T_TAGS + tags[s]];
    __syncthreads();
    for (int o = 128; o; o >>= 1) {
        if (threadIdx.x < o) red[threadIdx.x] += red[threadIdx.x + o];
        __syncthreads();
    }
    if (threadIdx.x == 0) g_partials[blockIdx.x] = red[0];
}

__global__ void __launch_bounds__(256) partialB_kernel(const float* __restrict__ weights,
                                                       const int* __restrict__ tags) {
    __shared__ float red[256];
    int s = blockIdx.x * 256 + threadIdx.x;
    float acc = 0.f;
    if (s < S_LEN - 1) acc = weights[(size_t)tags[s] * T_TAGS + tags[s + 1]];
    red[threadIdx.x] = acc;
    __syncthreads();
    for (int o = 128; o; o >>= 1) {
        if (threadIdx.x < o) red[threadIdx.x] += red[threadIdx.x + o];
        __syncthreads();
    }
    if (threadIdx.x == 0) g_partials[64 + blockIdx.x] = red[0];
}

__global__ void final2_kernel(float* __restrict__ out) {
    if (threadIdx.x != 0 || blockIdx.x != 0) return;
    float t = 0.f;
    for (int b = 0; b < 128; ++b) t += g_partials[b];
    out[S_LEN] = g_logZ - t;
}

// ---------------- launcher (gather at index 3 for the ncu capture slot) ----------------
extern "C" void kernel_launch(void* const* d_in, const int* in_sizes, int n_in,
                              void* d_out, int out_size) {
    const float* scores  = (const float*)d_in[0];
    const float* weights = (const float*)d_in[1];
    const int*   tags    = (const int*)d_in[2];
    float* out = (float*)d_out;

    topk_kernel<<<S_LEN, 256>>>(scores);                  // 0
    partialA_kernel<<<64, 256>>>(scores, tags);           // 1
    partialB_kernel<<<64, 256>>>(weights, tags);          // 2
    gather_kernel<<<NSTEP, 256>>>(weights);               // 3  <- ncu capture slot
    scan_kernel<<<2, 256>>>();                            // 4
    chunkmap_kernel<<<NCH, 64>>>();                       // 5
    finish_kernel<<<1, 32>>>();                           // 6
    emit_kernel<<<(S_LEN + 255) / 256, 256>>>(out);       // 7
    final2_kernel<<<1, 32>>>(out);                        // 8
}